// round 5
// baseline (speedup 1.0000x reference)
#include <cuda_runtime.h>
#include <cstdint>

// Fused: out[o*256+k][h][m] = sum_{i,j} w[i][k][j] * pad(xroll)[m+j]
// Grid = 896 blocks x 128 threads: bx -> (ich: 16, okt: 4, h: 14).
// Weights for the block (16 i x 128 k x 3 j) staged in SMEM via coalesced
// float4 loads (transposed to [il][j][k]); mainloop is LDS + f32x2 FMA only.
// Last of 16 ich-blocks per (okt,h) group reduces deterministically.

#define ILEN 16
#define NICH 16

__device__ float g_partial[NICH * 512 * 196];
__device__ unsigned int g_cnt[56];   // zero-init; reducer resets -> replay-safe

__device__ __forceinline__ uint64_t pk2(float v) {
    uint64_t r;
    asm("mov.b64 %0, {%1, %1};" : "=l"(r) : "r"(__float_as_uint(v)));
    return r;
}
__device__ __forceinline__ uint64_t ffma2(uint64_t a, uint64_t b, uint64_t c) {
    uint64_t d;
    asm("fma.rn.f32x2 %0, %1, %2, %3;" : "=l"(d) : "l"(a), "l"(b), "l"(c));
    return d;
}

__global__ __launch_bounds__(128) void fused_conv_kernel(const float* __restrict__ x,
                                                         const float* __restrict__ w,
                                                         float* __restrict__ out) {
    const int bx  = blockIdx.x;        // 0..895
    const int ich = bx & 15;
    const int okt = (bx >> 4) & 3;
    const int h   = bx >> 6;           // 0..13
    const int grp = bx >> 4;           // (okt,h) group, 0..55
    const int o   = okt >> 1;
    const int kt  = okt & 1;
    const int tx  = threadIdx.x;
    const int k   = kt * 128 + tx;     // global k within group
    const int n   = (h + 13) % 14;     // undo roll along H

    __shared__ float sw[ILEN * 384];   // [il][j][dk] : 24KB
    __shared__ float sxe[ILEN][16];    // padded/rolled row at tap mm
    __shared__ float sxo[ILEN][16];    // same shifted +1 (odd pairs)
    __shared__ int s_last;

    // ---- stage x rows (2KB) ----
    const float* xrow = x + ((size_t)(o * 256 + ich * ILEN) * 14 + n) * 14;
    {
        const int idx = tx;            // 128 threads cover 8 rows; loop 2x for 16
#pragma unroll
        for (int rep = 0; rep < 2; rep++) {
            const int id = idx + rep * 128;
            const int il = id >> 4;
            const int mm = id & 15;
            float ve = 0.f, vo = 0.f;
            if (mm >= 1 && mm <= 14) ve = xrow[(size_t)il * 196 + (mm + 12) % 14];
            if (mm <= 13)            vo = xrow[(size_t)il * 196 + (mm + 13) % 14];
            sxe[il][mm] = ve;
            sxo[il][mm] = vo;
        }
    }

    // ---- stage weights: 16 chunks of 384 contiguous floats (one per il) ----
    // global chunk base: (ich*ILEN + il)*768 + kt*384 ; layout in chunk: dk*3 + j
    {
        const float* wbase = w + (size_t)(ich * ILEN) * 768 + (size_t)kt * 384;
#pragma unroll
        for (int it = 0; it < 12; it++) {           // 12 float4 per thread, coalesced
            const int f4 = it * 128 + tx;           // 0..1535
            const int il = f4 / 96;                 // 96 float4 per chunk
            const int r4 = f4 - il * 96;
            const float4 v = *(const float4*)(wbase + (size_t)il * 768 + r4 * 4);
            const int r = r4 * 4;                   // flat float index in chunk
            float vv[4] = {v.x, v.y, v.z, v.w};
#pragma unroll
            for (int c = 0; c < 4; c++) {
                const int rr = r + c;
                const int dk = rr / 3;
                const int jj = rr - dk * 3;
                sw[il * 384 + jj * 128 + dk] = vv[c];
            }
        }
    }
    __syncthreads();

    uint64_t A[7];
#pragma unroll
    for (int p = 0; p < 7; p++) A[p] = 0ull;

#pragma unroll
    for (int il = 0; il < ILEN; ++il) {
        const uint64_t W0 = pk2(sw[il * 384 + 0 * 128 + tx]);
        const uint64_t W1 = pk2(sw[il * 384 + 1 * 128 + tx]);
        const uint64_t W2 = pk2(sw[il * 384 + 2 * 128 + tx]);

        const ulonglong2 e01 = *(const ulonglong2*)&sxe[il][0];
        const ulonglong2 e23 = *(const ulonglong2*)&sxe[il][4];
        const ulonglong2 e45 = *(const ulonglong2*)&sxe[il][8];
        const ulonglong2 e67 = *(const ulonglong2*)&sxe[il][12];
        const ulonglong2 o01 = *(const ulonglong2*)&sxo[il][0];
        const ulonglong2 o23 = *(const ulonglong2*)&sxo[il][4];
        const ulonglong2 o45 = *(const ulonglong2*)&sxo[il][8];
        const ulonglong2 o6_ = *(const ulonglong2*)&sxo[il][12];

        uint64_t E[8] = {e01.x, e01.y, e23.x, e23.y, e45.x, e45.y, e67.x, e67.y};
        uint64_t O[7] = {o01.x, o01.y, o23.x, o23.y, o45.x, o45.y, o6_.x};

#pragma unroll
        for (int p = 0; p < 7; p++) {
            A[p] = ffma2(W0, E[p],     A[p]);
            A[p] = ffma2(W1, O[p],     A[p]);
            A[p] = ffma2(W2, E[p + 1], A[p]);
        }
    }

    // ---- partials: [ich][c][196], c = o*256+k ----
    {
        float* pp = g_partial + ((size_t)ich * 512 + o * 256 + k) * 196 + h * 14;
#pragma unroll
        for (int p = 0; p < 7; p++)
            *(uint64_t*)&pp[2 * p] = A[p];
    }

    // ---- last-block-done reduction for this (okt, h) group ----
    __threadfence();                       // release partials
    if (tx == 0) {
        unsigned int old = atomicAdd(&g_cnt[grp], 1u);
        s_last = (old == NICH - 1);
    }
    __syncthreads();
    if (s_last) {
        __threadfence();                   // acquire
        const size_t off = ((size_t)(o * 256 + k)) * 196 + h * 14;
        float* op = out + off;
#pragma unroll
        for (int p = 0; p < 7; p++) {
            float2 s; s.x = 0.f; s.y = 0.f;
#pragma unroll
            for (int ic = 0; ic < NICH; ic++) {   // fixed order -> deterministic
                const float2 v = *(const float2*)&g_partial[(size_t)ic * 512 * 196 + off + 2 * p];
                s.x += v.x;
                s.y += v.y;
            }
            *(float2*)&op[2 * p] = s;
        }
        if (tx == 0) g_cnt[grp] = 0u;      // reset for next graph replay
    }
}

extern "C" void kernel_launch(void* const* d_in, const int* in_sizes, int n_in,
                              void* d_out, int out_size) {
    const float* x = (const float*)d_in[0];   // (1,512,14,14)
    const float* w = (const float*)d_in[1];   // (256,256,3)
    float* out = (float*)d_out;

    fused_conv_kernel<<<896, 128>>>(x, w, out);
}

// round 6
// speedup vs baseline: 4.7495x; 4.7495x over previous
#include <cuda_runtime.h>
#include <cstdint>

// Single fused kernel.
// out[o*256+k][h][m] = sum_{i,j} w[i][k][j] * xp[m+j], xp = padded/rolled row.
// Grid = 112 blocks (okt:4, h:14, mh:2). Block = 512 thr = 4 i-groups x 128 k.
// Each group accumulates 64 i's (8 chunks of 8, weights cp.async double-buffered
// into smem); cross-group reduction in smem, fixed order (deterministic).

#define CHUNKS   8
#define SW_FLOATS 12288              // one weight buffer: 32 rows * 384 floats
#define SXE_OFF  (2 * SW_FLOATS)     // float offset of sxe (256 x 16)
#define SXO_OFF  (SXE_OFF + 4096)    // sxo (256 x 16)
#define SMEM_BYTES ((2 * SW_FLOATS + 4096 + 4096) * 4)   // 128 KB

extern __shared__ float smem[];

__device__ __forceinline__ uint64_t pk2(float v) {
    uint64_t r;
    asm("mov.b64 %0, {%1, %1};" : "=l"(r) : "r"(__float_as_uint(v)));
    return r;
}
__device__ __forceinline__ uint64_t ffma2(uint64_t a, uint64_t b, uint64_t c) {
    uint64_t d;
    asm("fma.rn.f32x2 %0, %1, %2, %3;" : "=l"(d) : "l"(a), "l"(b), "l"(c));
    return d;
}
__device__ __forceinline__ void cp16(uint32_t s, const void* g) {
    asm volatile("cp.async.cg.shared.global [%0], [%1], 16;" :: "r"(s), "l"(g) : "memory");
}
__device__ __forceinline__ void cp_commit() {
    asm volatile("cp.async.commit_group;" ::: "memory");
}
template <int N> __device__ __forceinline__ void cp_wait() {
    asm volatile("cp.async.wait_group %0;" :: "n"(N) : "memory");
}

__global__ __launch_bounds__(512, 1)
void fused_conv_kernel(const float* __restrict__ x,
                       const float* __restrict__ w,
                       float* __restrict__ out) {
    const int okt = blockIdx.x / 28;
    const int rem = blockIdx.x % 28;
    const int h   = rem >> 1;
    const int mh  = rem & 1;           // m-half: 0 -> m 0..6, 1 -> m 7..13
    const int o   = okt >> 1;
    const int kt  = okt & 1;
    const int tid = threadIdx.x;
    const int g   = tid >> 7;          // i-group 0..3
    const int tx  = tid & 127;         // k within tile
    const int n   = (h + 13) % 14;     // undo roll along H

    const uint32_t sw_u32 = (uint32_t)__cvta_generic_to_shared(smem);

    // ---- issue first two weight chunk copies (cp.async, no transpose) ----
    // chunk c: 32 rows (4 groups x 8 il), row r -> i = (r>>3)*64 + c*8 + (r&7),
    // 384 contiguous floats (kt half of w row i). 3072 f4 per chunk, 6 per thread.
    const float* wb = w + (size_t)kt * 384;
#pragma unroll
    for (int c0 = 0; c0 < 2; c0++) {
#pragma unroll
        for (int it = 0; it < 6; it++) {
            const int f4 = it * 512 + tid;
            const int r = f4 / 96;
            const int within = f4 % 96;
            const int i = (r >> 3) * 64 + c0 * 8 + (r & 7);
            cp16(sw_u32 + (uint32_t)(c0 * SW_FLOATS + r * 384 + within * 4) * 4,
                 wb + (size_t)i * 768 + within * 4);
        }
        cp_commit();
    }

    // ---- stage x rows, pre-shifted by 6*mh so operand pairs are aligned ----
    // sxe[i][mm] = xp[mm + 6*mh], sxo[i][mm] = xp[mm + 1 + 6*mh]
    // xp[a] = (a in [1,14]) ? x[o*256+i][n][(a+12)%14] : 0
    {
        const float* xbase = x + ((size_t)o * 256) * 196 + n * 14;
        const int sh = 6 * mh;
#pragma unroll
        for (int rep = 0; rep < 8; rep++) {
            const int idx = rep * 512 + tid;       // 0..4095
            const int i = idx >> 4;
            const int mm = idx & 15;
            const int a = mm + sh;
            const int b = a + 1;
            float ve = 0.f, vo = 0.f;
            if (a >= 1 && a <= 14) ve = xbase[(size_t)i * 196 + (a + 12) % 14];
            if (b <= 14)           vo = xbase[(size_t)i * 196 + (b + 12) % 14];
            smem[SXE_OFF + idx] = ve;
            smem[SXO_OFF + idx] = vo;
        }
    }

    uint64_t A[4];
#pragma unroll
    for (int p = 0; p < 4; p++) A[p] = 0ull;

    // ---- main loop over 8 chunks, double-buffered ----
    for (int c = 0; c < CHUNKS; c++) {
        if (c == CHUNKS - 1) cp_wait<0>(); else cp_wait<1>();
        __syncthreads();                       // chunk c visible (+ x staging on c=0)

        const int buf = c & 1;
        const float* swp = smem + buf * SW_FLOATS + (g * 8) * 384 + tx * 3;
        const float* xe  = smem + SXE_OFF + (size_t)(g * 64 + c * 8) * 16;
        const float* xo  = smem + SXO_OFF + (size_t)(g * 64 + c * 8) * 16;

#pragma unroll
        for (int il = 0; il < 8; il++) {
            const uint64_t W0 = pk2(swp[il * 384 + 0]);
            const uint64_t W1 = pk2(swp[il * 384 + 1]);
            const uint64_t W2 = pk2(swp[il * 384 + 2]);

            const ulonglong2 e01 = *(const ulonglong2*)(xe + il * 16);
            const ulonglong2 e23 = *(const ulonglong2*)(xe + il * 16 + 4);
            const uint64_t   e4  = *(const uint64_t*)  (xe + il * 16 + 8);
            const ulonglong2 o01 = *(const ulonglong2*)(xo + il * 16);
            const ulonglong2 o23 = *(const ulonglong2*)(xo + il * 16 + 4);

            uint64_t E[5] = {e01.x, e01.y, e23.x, e23.y, e4};
            uint64_t O[4] = {o01.x, o01.y, o23.x, o23.y};

#pragma unroll
            for (int p = 0; p < 4; p++) {
                A[p] = ffma2(W0, E[p],     A[p]);
                A[p] = ffma2(W1, O[p],     A[p]);
                A[p] = ffma2(W2, E[p + 1], A[p]);
            }
        }
        __syncthreads();                       // done reading buf before refill
        if (c + 2 < CHUNKS) {
#pragma unroll
            for (int it = 0; it < 6; it++) {
                const int f4 = it * 512 + tid;
                const int r = f4 / 96;
                const int within = f4 % 96;
                const int i = (r >> 3) * 64 + (c + 2) * 8 + (r & 7);
                cp16(sw_u32 + (uint32_t)(buf * SW_FLOATS + r * 384 + within * 4) * 4,
                     wb + (size_t)i * 768 + within * 4);
            }
            cp_commit();
        }
    }

    // ---- cross-group reduction in smem (reuse weight buffers) ----
    // ps[(g*128 + k)*4 + p] : float2 partial for pair p (m = 6*mh + 2p, +1)
    uint64_t* ps = (uint64_t*)smem;
#pragma unroll
    for (int p = 0; p < 4; p++)
        ps[((size_t)(g * 128 + tx) << 2) + p] = A[p];
    __syncthreads();

    {
        const int k = tid >> 2;                // 0..127
        const int p = tid & 3;
        const float2 a = ((const float2*)ps)[((0 * 128 + k) << 2) + p];
        const float2 b = ((const float2*)ps)[((1 * 128 + k) << 2) + p];
        const float2 c2 = ((const float2*)ps)[((2 * 128 + k) << 2) + p];
        const float2 d = ((const float2*)ps)[((3 * 128 + k) << 2) + p];
        float vlo = ((a.x + b.x) + c2.x) + d.x;    // fixed order -> deterministic
        float vhi = ((a.y + b.y) + c2.y) + d.y;

        const int cg   = o * 256 + kt * 128 + k;
        const int base = cg * 196 + h * 14;
        const int m0   = 6 * mh + 2 * p;
        if (mh == 0) {
            if (p < 3) { out[base + m0] = vlo; out[base + m0 + 1] = vhi; }
            else       { out[base + 6] = vlo; }
        } else {
            if (p == 0) { out[base + 7] = vhi; }
            else        { out[base + m0] = vlo; out[base + m0 + 1] = vhi; }
        }
    }
}

extern "C" void kernel_launch(void* const* d_in, const int* in_sizes, int n_in,
                              void* d_out, int out_size) {
    const float* x = (const float*)d_in[0];   // (1,512,14,14)
    const float* w = (const float*)d_in[1];   // (256,256,3)
    float* out = (float*)d_out;

    cudaFuncSetAttribute(fused_conv_kernel,
                         cudaFuncAttributeMaxDynamicSharedMemorySize, SMEM_BYTES);
    fused_conv_kernel<<<112, 512, SMEM_BYTES>>>(x, w, out);
}